// round 9
// baseline (speedup 1.0000x reference)
#include <cuda_runtime.h>
#include <cuda_bf16.h>
#include <cstdint>
#include <cstddef>

#define THREADS 256

// Scratch activations (fp32)
__device__ float g_h0[8192u * 2048u];
__device__ float g_h2[8192u * 2048u];

// Packed pre-swizzled bf16 hi/lo weights:
// sw blocks: per (layer, ntile, kchunk64, sub): 32KB = [hi 16KB | lo 16KB]
// bw blocks: per (layer, ntile, kchunk64): 32KB
__device__ __align__(128) char g_swp[167772160];   // 160MB
__device__ __align__(128) char g_bwp[20971520];    // 20MB
// Packed A-blocks (per layer, reused): per (mtile, kchunk64, sub 0..8): 32KB
__device__ __align__(128) char g_ab[603979776];

// Gaussian basis recurrence: e_g = e0 * u^g * exp(-2e-4*g^2)
__constant__ float RAT[7] = {0.99980002f, 0.99940018f, 0.99900050f,
                             0.99860098f, 0.99820162f, 0.99780242f, 0.99740338f};

// ---------------- threefry2x32 (JAX-compatible, validated) ----------------
__device__ __forceinline__ uint32_t rotl32d(uint32_t v, int d) {
    return __funnelshift_l(v, v, d);
}
__device__ __forceinline__ void threefry2x32_dev(uint32_t k0, uint32_t k1,
                                                 uint32_t c0, uint32_t c1,
                                                 uint32_t& o0, uint32_t& o1) {
    uint32_t ks2 = k0 ^ k1 ^ 0x1BD11BDAu;
    uint32_t x0 = c0 + k0, x1 = c1 + k1;
#define TF_RND(r) { x0 += x1; x1 = rotl32d(x1, r); x1 ^= x0; }
    TF_RND(13) TF_RND(15) TF_RND(26) TF_RND(6)
    x0 += k1;  x1 += ks2 + 1u;
    TF_RND(17) TF_RND(29) TF_RND(16) TF_RND(24)
    x0 += ks2; x1 += k0 + 2u;
    TF_RND(13) TF_RND(15) TF_RND(26) TF_RND(6)
    x0 += k0;  x1 += k1 + 3u;
    TF_RND(17) TF_RND(29) TF_RND(16) TF_RND(24)
    x0 += k1;  x1 += ks2 + 4u;
    TF_RND(13) TF_RND(15) TF_RND(26) TF_RND(6)
    x0 += ks2; x1 += k0 + 5u;
#undef TF_RND
    o0 = x0; o1 = x1;
}
static inline uint32_t rotl32h(uint32_t v, int d) {
    return (v << d) | (v >> (32 - d));
}
static void threefry2x32_host(uint32_t k0, uint32_t k1, uint32_t c0, uint32_t c1,
                              uint32_t& o0, uint32_t& o1) {
    uint32_t ks2 = k0 ^ k1 ^ 0x1BD11BDAu;
    uint32_t x0 = c0 + k0, x1 = c1 + k1;
#define TF_RND(r) { x0 += x1; x1 = rotl32h(x1, r); x1 ^= x0; }
    TF_RND(13) TF_RND(15) TF_RND(26) TF_RND(6)
    x0 += k1;  x1 += ks2 + 1u;
    TF_RND(17) TF_RND(29) TF_RND(16) TF_RND(24)
    x0 += ks2; x1 += k0 + 2u;
    TF_RND(13) TF_RND(15) TF_RND(26) TF_RND(6)
    x0 += k0;  x1 += k1 + 3u;
    TF_RND(17) TF_RND(29) TF_RND(16) TF_RND(24)
    x0 += k1;  x1 += ks2 + 4u;
    TF_RND(13) TF_RND(15) TF_RND(26) TF_RND(6)
    x0 += ks2; x1 += k0 + 5u;
#undef TF_RND
    o0 = x0; o1 = x1;
}

// ---------------- helpers ----------------
__device__ __forceinline__ uint32_t smem_u32(const void* p) {
    uint32_t a;
    asm("{ .reg .u64 t; cvta.to.shared.u64 t, %1; cvt.u32.u64 %0, t; }"
        : "=r"(a) : "l"(p));
    return a;
}
#define SW128(o) ((o) ^ ((((uint32_t)(o)) >> 3) & 0x70))

#define LDSM4(rv, a) \
    asm volatile("ldmatrix.sync.aligned.m8n8.x4.shared.b16 {%0,%1,%2,%3}, [%4];" \
        : "=r"((rv)[0]), "=r"((rv)[1]), "=r"((rv)[2]), "=r"((rv)[3]) \
        : "r"(a))

#define MMA_BF16(c, a, b0, b1) \
    asm volatile("mma.sync.aligned.m16n8k16.row.col.f32.bf16.bf16.f32 " \
        "{%0,%1,%2,%3}, {%4,%5,%6,%7}, {%8,%9}, {%0,%1,%2,%3};" \
        : "+f"((c)[0]), "+f"((c)[1]), "+f"((c)[2]), "+f"((c)[3]) \
        : "r"((a)[0]), "r"((a)[1]), "r"((a)[2]), "r"((a)[3]), "r"(b0), "r"(b1))

#define CP_ASYNC16(dst, src) \
    asm volatile("cp.async.cg.shared.global [%0], [%1], 16;" \
                 :: "r"((uint32_t)(dst)), "l"(src) : "memory")
#define CP_COMMIT() asm volatile("cp.async.commit_group;" ::: "memory")
#define CP_WAIT0()  asm volatile("cp.async.wait_group 0;" ::: "memory")
#define CP_WAIT1()  asm volatile("cp.async.wait_group 1;" ::: "memory")

__device__ __forceinline__ void bfsplit2(float a, float b, uint32_t& hi2, uint32_t& lo2) {
    asm("cvt.rn.bf16x2.f32 %0, %1, %2;" : "=r"(hi2) : "f"(b), "f"(a));
    __nv_bfloat162 hv = *reinterpret_cast<__nv_bfloat162*>(&hi2);
    float ra = a - __bfloat162float(hv.x);
    float rb = b - __bfloat162float(hv.y);
    asm("cvt.rn.bf16x2.f32 %0, %1, %2;" : "=r"(lo2) : "f"(rb), "f"(ra));
}

// ---------------- pack kernels ----------------
__global__ void pack_sw_kernel(const float* __restrict__ sw, char* __restrict__ dst,
                               int I, int O) {
    size_t idx = (size_t)blockIdx.x * blockDim.x + threadIdx.x;
    size_t total = (size_t)I * O * 4;
    if (idx >= total) return;
    int g2 = (int)(idx & 3) * 2;
    size_t rem = idx >> 2;
    int o = (int)(rem % O);
    int i = (int)(rem / O);
    float2 wv = *reinterpret_cast<const float2*>(&sw[((size_t)i * O + o) * 8 + g2]);
    uint32_t hw, lw;
    bfsplit2(wv.x, wv.y, hw, lw);
    int t = o >> 7, n = o & 127, c = i >> 6, s = (i >> 3) & 7, ii = i & 7;
    size_t blk = (((size_t)t * (I >> 6) + c) * 8 + s) * 32768;
    uint32_t off = SW128((uint32_t)(n * 128 + (ii * 8 + g2) * 2));
    *reinterpret_cast<uint32_t*>(dst + blk + off) = hw;
    *reinterpret_cast<uint32_t*>(dst + blk + 16384 + off) = lw;
}

__global__ void pack_bw_kernel(const float* __restrict__ bw, char* __restrict__ dst,
                               int I, int O) {
    size_t idx = (size_t)blockIdx.x * blockDim.x + threadIdx.x;
    size_t total = (size_t)O * (I >> 1);
    if (idx >= total) return;
    int o = (int)(idx % O);
    int kp = (int)(idx / O);
    float b0 = bw[(size_t)(2 * kp) * O + o];
    float b1 = bw[(size_t)(2 * kp + 1) * O + o];
    uint32_t hw, lw;
    bfsplit2(b0, b1, hw, lw);
    int t = o >> 7, n = o & 127;
    int c = (2 * kp) >> 6, klocal = (2 * kp) & 63;
    size_t blk = ((size_t)t * (I >> 6) + c) * 32768;
    uint32_t off = SW128((uint32_t)(n * 128 + klocal * 2));
    *reinterpret_cast<uint32_t*>(dst + blk + off) = hw;
    *reinterpret_cast<uint32_t*>(dst + blk + 16384 + off) = lw;
}

__global__ void pack_bases_kernel(const float* __restrict__ act,
                                  char* __restrict__ ab, int I, int nkc) {
    int bid = blockIdx.x;
    int sub = bid & 7;
    int t = bid >> 3;
    int kc = t % nkc;
    int mt = t / nkc;
    char* blk = ab + (((size_t)mt * nkc + kc) * 9 + sub) * 32768;
    int tid = threadIdx.x;
    #pragma unroll
    for (int rr = 0; rr < 4; ++rr) {
        int v = rr * 256 + tid;
        int mloc = v >> 3, il = v & 7;
        float xv = act[(size_t)(mt * 128 + mloc) * I + kc * 64 + sub * 8 + il];
        float d = xv + 0.044f;
        float e = __expf(-3.125f * d * d);
        float u = __expf(0.05f * d);
        float vv[8];
        vv[0] = e;
        #pragma unroll
        for (int g = 1; g < 8; ++g) vv[g] = vv[g - 1] * u * RAT[g - 1];
        uint32_t hw[4], lw[4];
        #pragma unroll
        for (int qq = 0; qq < 4; ++qq)
            bfsplit2(vv[2 * qq], vv[2 * qq + 1], hw[qq], lw[qq]);
        uint32_t off = SW128((uint32_t)(mloc * 128 + il * 16));
        *reinterpret_cast<uint4*>(blk + off) = make_uint4(hw[0], hw[1], hw[2], hw[3]);
        *reinterpret_cast<uint4*>(blk + 16384 + off) = make_uint4(lw[0], lw[1], lw[2], lw[3]);
    }
}

__global__ void pack_x_kernel(const float* __restrict__ act,
                              char* __restrict__ ab, int I, int nkc) {
    int bid = blockIdx.x;
    int kc = bid % nkc;
    int mt = bid / nkc;
    char* blk = ab + (((size_t)mt * nkc + kc) * 9 + 8) * 32768;
    int tid = threadIdx.x;
    #pragma unroll
    for (int rr = 0; rr < 8; ++rr) {
        int v = rr * 256 + tid;
        int mloc = v >> 4, c4 = v & 15;
        float4 xv = *reinterpret_cast<const float4*>(
            &act[(size_t)(mt * 128 + mloc) * I + kc * 64 + c4 * 4]);
        uint32_t h0w, l0w, h1w, l1w;
        bfsplit2(xv.x, xv.y, h0w, l0w);
        bfsplit2(xv.z, xv.w, h1w, l1w);
        uint32_t off = SW128((uint32_t)(mloc * 128 + c4 * 8));
        *reinterpret_cast<uint2*>(blk + off) = make_uint2(h0w, h1w);
        *reinterpret_cast<uint2*>(blk + 16384 + off) = make_uint2(l0w, l1w);
    }
}

// ---------------- SMEM: 3-stage ring, 64KB per stage ----------------
static constexpr int STAGE_STRIDE = 65536;
static constexpr int NSTAGE = 3;
static constexpr int SMEM_SZ = NSTAGE * STAGE_STRIDE;   // 192KB
static constexpr int SMEM_DYN = SMEM_SZ + 1024;

// ---------------- main kernel: 8 warps (2x4), warp tile 64x32 ----------------
__global__ __launch_bounds__(THREADS, 1)
void kan_mma_kernel(const char* __restrict__ ab,
                    const char* __restrict__ swp,
                    const char* __restrict__ bwp,
                    const float* __restrict__ sbp,
                    const float* __restrict__ ssp,
                    const float* __restrict__ snp,
                    float* __restrict__ outp,
                    int nkc, int O,
                    uint32_t nk0, uint32_t nk1) {
    extern __shared__ char raw[];
    const uint32_t rawu = smem_u32(raw);
    const uint32_t sbase = (rawu + 1023u) & ~1023u;

    const int tid = threadIdx.x;
    const int wid = tid >> 5;
    const int lid = tid & 31;
    const int wm  = wid >> 2;       // 0..1 (64 rows each)
    const int wn  = wid & 3;        // 0..3 (32 cols each)
    const int m0  = blockIdx.y * 128;
    const int n0  = blockIdx.x * 128;   // n fastest
    const int mt  = blockIdx.y;

    const int q = lid >> 3, r = lid & 7;
    const int rowA_l = r + (q & 1) * 8;
    const int kselA  = (q >> 1) * 16;
    const int rowB_l = r + (q >> 1) * 8;
    const int kselB  = (q & 1) * 16;

    float accS[4][4][4];
    float accB[4][4][4];
    #pragma unroll
    for (int a = 0; a < 4; ++a)
        #pragma unroll
        for (int b = 0; b < 4; ++b)
            #pragma unroll
            for (int e = 0; e < 4; ++e) { accS[a][b][e] = 0.f; accB[a][b][e] = 0.f; }

    const size_t a_tile = (size_t)mt * nkc;
    const size_t b_tile = (size_t)(n0 >> 7) * nkc;
    const int total = nkc * 9;

    auto issue_stage = [&](int s) {
        int kc = s / 9, sub = s - kc * 9;
        uint32_t dst = sbase + (s % NSTAGE) * STAGE_STRIDE;
        const char* asrc = ab + ((a_tile + kc) * 9 + sub) * 32768;
        const char* bsrc = (sub < 8)
            ? swp + (((b_tile + kc) * 8) + sub) * 32768
            : bwp + (b_tile + kc) * 32768;
        #pragma unroll
        for (int rr = 0; rr < 8; ++rr) {
            uint32_t off = (uint32_t)(rr * THREADS + tid) * 16;
            CP_ASYNC16(dst + off, asrc + off);
        }
        #pragma unroll
        for (int rr = 0; rr < 8; ++rr) {
            uint32_t off = (uint32_t)(rr * THREADS + tid) * 16;
            CP_ASYNC16(dst + 32768 + off, bsrc + off);
        }
        CP_COMMIT();
    };

    auto do_mma = [&](int buf, float (&acc)[4][4][4]) {
        const uint32_t Ah = sbase + buf * STAGE_STRIDE;
        const uint32_t Al = Ah + 16384;
        const uint32_t Bh = Ah + 32768;
        const uint32_t Bl = Ah + 49152;
        #pragma unroll
        for (int k16 = 0; k16 < 4; ++k16) {
            const int kbyt = k16 * 32;
            uint32_t ah[4][4], al[4][4];
            #pragma unroll
            for (int mf = 0; mf < 4; ++mf) {
                int m = wm * 64 + mf * 16 + rowA_l;
                uint32_t off = (uint32_t)(m * 128)
                             + (((uint32_t)(kbyt + kselA)) ^ ((m * 16) & 0x70));
                LDSM4(ah[mf], Ah + off);
                LDSM4(al[mf], Al + off);
            }
            uint32_t bh[2][4], bl[2][4];
            #pragma unroll
            for (int nb = 0; nb < 2; ++nb) {
                int n = wn * 32 + nb * 16 + rowB_l;
                uint32_t off = (uint32_t)(n * 128)
                             + (((uint32_t)(kbyt + kselB)) ^ ((n * 16) & 0x70));
                LDSM4(bh[nb], Bh + off);
                LDSM4(bl[nb], Bl + off);
            }
            #pragma unroll
            for (int mf = 0; mf < 4; ++mf)
                #pragma unroll
                for (int nf = 0; nf < 4; ++nf) {
                    const int nb = nf >> 1, ri = (nf & 1) * 2;
                    MMA_BF16(acc[mf][nf], ah[mf], bh[nb][ri], bh[nb][ri + 1]);
                    MMA_BF16(acc[mf][nf], ah[mf], bl[nb][ri], bl[nb][ri + 1]);
                    MMA_BF16(acc[mf][nf], al[mf], bh[nb][ri], bh[nb][ri + 1]);
                }
        }
    };

    issue_stage(0);
    issue_stage(1);
    for (int s = 0; s < total; ++s) {
        if (s < total - 1) { CP_WAIT1(); } else { CP_WAIT0(); }
        __syncthreads();
        if (s + 2 < total) issue_stage(s + 2);   // copies overlap this stage's MMA
        int sub = s % 9;
        if (sub == 8) do_mma(s % NSTAGE, accB);
        else          do_mma(s % NSTAGE, accS);
    }

    // ---------------- epilogue ----------------
    const float snv = *snp;
    const int rq = lid >> 2, cq = (lid & 3) * 2;
    #pragma unroll
    for (int mf = 0; mf < 4; ++mf) {
        #pragma unroll
        for (int nf = 0; nf < 4; ++nf) {
            #pragma unroll
            for (int half = 0; half < 2; ++half) {
                int b = m0 + wm * 64 + mf * 16 + rq + half * 8;
                int obase = n0 + wn * 32 + nf * 8 + cq;
                float2 res;
                #pragma unroll
                for (int e = 0; e < 2; ++e) {
                    int o = obase + e;
                    float sv = accS[mf][nf][half * 2 + e];
                    float bv = accB[mf][nf][half * 2 + e];
                    float sg = 1.0f / (1.0f + __expf(-bv));
                    uint32_t li = (uint32_t)b * (uint32_t)O + (uint32_t)o;
                    uint32_t r0, r1;
                    threefry2x32_dev(nk0, nk1, 0u, li, r0, r1);
                    uint32_t bits = r0 ^ r1;
                    float f = __uint_as_float((bits >> 9) | 0x3f800000u) - 1.0f;
                    float uu = fmaxf(-0.99999994f, fmaf(f, 2.0f, -0.99999994f));
                    float nz = 1.41421356f * erfinvf(uu);
                    float val = bv * sg * sbp[o] + sv * ssp[o] + nz * snv;
                    if (e == 0) res.x = val; else res.y = val;
                }
                *reinterpret_cast<float2*>(&outp[(size_t)b * O + obase]) = res;
            }
        }
    }
}

// ---------------- launch ----------------
extern "C" void kernel_launch(void* const* d_in, const int* in_sizes, int n_in,
                              void* d_out, int out_size) {
    const float* x = (const float*)d_in[0];
    const float* sw[4]; const float* bw[4]; const float* sb[4];
    const float* ss[4]; const float* sn[4];
    for (int li = 0; li < 4; ++li) {
        sw[li] = (const float*)d_in[1 + 5 * li + 0];
        bw[li] = (const float*)d_in[1 + 5 * li + 1];
        sb[li] = (const float*)d_in[1 + 5 * li + 2];
        ss[li] = (const float*)d_in[1 + 5 * li + 3];
        sn[li] = (const float*)d_in[1 + 5 * li + 4];
    }
    const int B = in_sizes[0] / 1024;   // 8192
    float* out  = (float*)d_out;
    float* xrec = out;
    float* z    = out + (size_t)B * 1024;

    float* h0; cudaGetSymbolAddress((void**)&h0, g_h0);
    float* h2; cudaGetSymbolAddress((void**)&h2, g_h2);
    char* swp; cudaGetSymbolAddress((void**)&swp, g_swp);
    char* bwp; cudaGetSymbolAddress((void**)&bwp, g_bwp);
    char* ab;  cudaGetSymbolAddress((void**)&ab, g_ab);

    const int Is[4] = {1024, 2048, 256, 2048};
    const int Os[4] = {2048, 256, 2048, 1024};
    size_t sw_off[4], bw_off[4];
    size_t so = 0, bo = 0;
    for (int li = 0; li < 4; ++li) {
        sw_off[li] = so; bw_off[li] = bo;
        so += (size_t)(Os[li] / 128) * (Is[li] / 64) * 8 * 32768;
        bo += (size_t)(Os[li] / 128) * (Is[li] / 64) * 32768;
    }

    uint32_t fk0[4], fk1[4];
    for (int li = 0; li < 4; ++li)
        threefry2x32_host(0u, 42u, 0u, (uint32_t)li, fk0[li], fk1[li]);

    cudaFuncSetAttribute(kan_mma_kernel,
                         cudaFuncAttributeMaxDynamicSharedMemorySize, SMEM_DYN);

    const int mtiles = B / 128;
    dim3 blk(THREADS);
    const float* ins[4]  = {x, h0, z, h2};
    float* outs[4]       = {h0, z, h2, xrec};

    auto pack_sw = [&](int li) {
        size_t tot = (size_t)Is[li] * Os[li] * 4;
        pack_sw_kernel<<<(unsigned)((tot + 255) / 256), 256>>>(
            sw[li], swp + sw_off[li], Is[li], Os[li]);
    };
    auto pack_bw = [&](int li) {
        size_t totb = (size_t)Os[li] * (Is[li] / 2);
        pack_bw_kernel<<<(unsigned)((totb + 255) / 256), 256>>>(
            bw[li], bwp + bw_off[li], Is[li], Os[li]);
    };
    auto pack_a = [&](int li) {
        const int nkc = Is[li] / 64;
        pack_bases_kernel<<<(unsigned)(mtiles * nkc * 8), 256>>>(ins[li], ab, Is[li], nkc);
        pack_x_kernel<<<(unsigned)(mtiles * nkc), 256>>>(ins[li], ab, Is[li], nkc);
    };
    auto run_main = [&](int li) {
        dim3 g(Os[li] / 128, mtiles);
        kan_mma_kernel<<<g, blk, SMEM_DYN>>>(
            ab, swp + sw_off[li], bwp + bw_off[li],
            sb[li], ss[li], sn[li], outs[li],
            Is[li] / 64, Os[li], fk0[li], fk1[li]);
    };

    // Launch order: main0 at index 5 so ncu (-s 5 -c 1) captures it.
    pack_sw(0);       // 0
    pack_bw(0);       // 1
    pack_a(0);        // 2,3
    pack_sw(1);       // 4
    run_main(0);      // 5  ← ncu
    pack_bw(1);       // 6
    pack_sw(2);       // 7
    pack_bw(2);       // 8
    pack_sw(3);       // 9
    pack_bw(3);       // 10
    pack_a(1);        // 11,12
    run_main(1);      // 13
    pack_a(2);        // 14,15
    run_main(2);      // 16
    pack_a(3);        // 17,18
    run_main(3);      // 19
}

// round 10
// speedup vs baseline: 1.0443x; 1.0443x over previous
#include <cuda_runtime.h>
#include <cuda_bf16.h>
#include <cstdint>
#include <cstddef>

#define THREADS 512

// Scratch activations (fp32)
__device__ float g_h0[8192u * 2048u];
__device__ float g_h2[8192u * 2048u];

// Packed pre-swizzled bf16 hi/lo weights:
// sw blocks: per (layer, ntile, kchunk64, sub): 32KB = [hi 16KB | lo 16KB]
// bw blocks: per (layer, ntile, kchunk64): 32KB
__device__ __align__(128) char g_swp[167772160];   // 160MB
__device__ __align__(128) char g_bwp[20971520];    // 20MB
// Packed A-blocks (per layer, reused): per (mtile, kchunk64, sub 0..8): 32KB
__device__ __align__(128) char g_ab[603979776];

// Gaussian basis recurrence: e_g = e0 * u^g * exp(-2e-4*g^2)
__constant__ float RAT[7] = {0.99980002f, 0.99940018f, 0.99900050f,
                             0.99860098f, 0.99820162f, 0.99780242f, 0.99740338f};

// ---------------- threefry2x32 (JAX-compatible, validated) ----------------
__device__ __forceinline__ uint32_t rotl32d(uint32_t v, int d) {
    return __funnelshift_l(v, v, d);
}
__device__ __forceinline__ void threefry2x32_dev(uint32_t k0, uint32_t k1,
                                                 uint32_t c0, uint32_t c1,
                                                 uint32_t& o0, uint32_t& o1) {
    uint32_t ks2 = k0 ^ k1 ^ 0x1BD11BDAu;
    uint32_t x0 = c0 + k0, x1 = c1 + k1;
#define TF_RND(r) { x0 += x1; x1 = rotl32d(x1, r); x1 ^= x0; }
    TF_RND(13) TF_RND(15) TF_RND(26) TF_RND(6)
    x0 += k1;  x1 += ks2 + 1u;
    TF_RND(17) TF_RND(29) TF_RND(16) TF_RND(24)
    x0 += ks2; x1 += k0 + 2u;
    TF_RND(13) TF_RND(15) TF_RND(26) TF_RND(6)
    x0 += k0;  x1 += k1 + 3u;
    TF_RND(17) TF_RND(29) TF_RND(16) TF_RND(24)
    x0 += k1;  x1 += ks2 + 4u;
    TF_RND(13) TF_RND(15) TF_RND(26) TF_RND(6)
    x0 += ks2; x1 += k0 + 5u;
#undef TF_RND
    o0 = x0; o1 = x1;
}
static inline uint32_t rotl32h(uint32_t v, int d) {
    return (v << d) | (v >> (32 - d));
}
static void threefry2x32_host(uint32_t k0, uint32_t k1, uint32_t c0, uint32_t c1,
                              uint32_t& o0, uint32_t& o1) {
    uint32_t ks2 = k0 ^ k1 ^ 0x1BD11BDAu;
    uint32_t x0 = c0 + k0, x1 = c1 + k1;
#define TF_RND(r) { x0 += x1; x1 = rotl32h(x1, r); x1 ^= x0; }
    TF_RND(13) TF_RND(15) TF_RND(26) TF_RND(6)
    x0 += k1;  x1 += ks2 + 1u;
    TF_RND(17) TF_RND(29) TF_RND(16) TF_RND(24)
    x0 += ks2; x1 += k0 + 2u;
    TF_RND(13) TF_RND(15) TF_RND(26) TF_RND(6)
    x0 += k0;  x1 += k1 + 3u;
    TF_RND(17) TF_RND(29) TF_RND(16) TF_RND(24)
    x0 += k1;  x1 += ks2 + 4u;
    TF_RND(13) TF_RND(15) TF_RND(26) TF_RND(6)
    x0 += ks2; x1 += k0 + 5u;
#undef TF_RND
    o0 = x0; o1 = x1;
}

// ---------------- helpers ----------------
__device__ __forceinline__ uint32_t smem_u32(const void* p) {
    uint32_t a;
    asm("{ .reg .u64 t; cvta.to.shared.u64 t, %1; cvt.u32.u64 %0, t; }"
        : "=r"(a) : "l"(p));
    return a;
}
#define SW128(o) ((o) ^ ((((uint32_t)(o)) >> 3) & 0x70))

#define LDSM4(rv, a) \
    asm volatile("ldmatrix.sync.aligned.m8n8.x4.shared.b16 {%0,%1,%2,%3}, [%4];" \
        : "=r"((rv)[0]), "=r"((rv)[1]), "=r"((rv)[2]), "=r"((rv)[3]) \
        : "r"(a))

#define MMA_BF16(c, a, b0, b1) \
    asm volatile("mma.sync.aligned.m16n8k16.row.col.f32.bf16.bf16.f32 " \
        "{%0,%1,%2,%3}, {%4,%5,%6,%7}, {%8,%9}, {%0,%1,%2,%3};" \
        : "+f"((c)[0]), "+f"((c)[1]), "+f"((c)[2]), "+f"((c)[3]) \
        : "r"((a)[0]), "r"((a)[1]), "r"((a)[2]), "r"((a)[3]), "r"(b0), "r"(b1))

#define CP_ASYNC16(dst, src) \
    asm volatile("cp.async.cg.shared.global [%0], [%1], 16;" \
                 :: "r"((uint32_t)(dst)), "l"(src) : "memory")
#define CP_COMMIT() asm volatile("cp.async.commit_group;" ::: "memory")
#define CP_WAIT0()  asm volatile("cp.async.wait_group 0;" ::: "memory")
#define CP_WAIT1()  asm volatile("cp.async.wait_group 1;" ::: "memory")

__device__ __forceinline__ void bfsplit2(float a, float b, uint32_t& hi2, uint32_t& lo2) {
    asm("cvt.rn.bf16x2.f32 %0, %1, %2;" : "=r"(hi2) : "f"(b), "f"(a));
    __nv_bfloat162 hv = *reinterpret_cast<__nv_bfloat162*>(&hi2);
    float ra = a - __bfloat162float(hv.x);
    float rb = b - __bfloat162float(hv.y);
    asm("cvt.rn.bf16x2.f32 %0, %1, %2;" : "=r"(lo2) : "f"(rb), "f"(ra));
}

// ---------------- pack kernels ----------------
__global__ void pack_sw_kernel(const float* __restrict__ sw, char* __restrict__ dst,
                               int I, int O) {
    size_t idx = (size_t)blockIdx.x * blockDim.x + threadIdx.x;
    size_t total = (size_t)I * O * 4;
    if (idx >= total) return;
    int g2 = (int)(idx & 3) * 2;
    size_t rem = idx >> 2;
    int o = (int)(rem % O);
    int i = (int)(rem / O);
    float2 wv = *reinterpret_cast<const float2*>(&sw[((size_t)i * O + o) * 8 + g2]);
    uint32_t hw, lw;
    bfsplit2(wv.x, wv.y, hw, lw);
    int t = o >> 7, n = o & 127, c = i >> 6, s = (i >> 3) & 7, ii = i & 7;
    size_t blk = (((size_t)t * (I >> 6) + c) * 8 + s) * 32768;
    uint32_t off = SW128((uint32_t)(n * 128 + (ii * 8 + g2) * 2));
    *reinterpret_cast<uint32_t*>(dst + blk + off) = hw;
    *reinterpret_cast<uint32_t*>(dst + blk + 16384 + off) = lw;
}

__global__ void pack_bw_kernel(const float* __restrict__ bw, char* __restrict__ dst,
                               int I, int O) {
    size_t idx = (size_t)blockIdx.x * blockDim.x + threadIdx.x;
    size_t total = (size_t)O * (I >> 1);
    if (idx >= total) return;
    int o = (int)(idx % O);
    int kp = (int)(idx / O);
    float b0 = bw[(size_t)(2 * kp) * O + o];
    float b1 = bw[(size_t)(2 * kp + 1) * O + o];
    uint32_t hw, lw;
    bfsplit2(b0, b1, hw, lw);
    int t = o >> 7, n = o & 127;
    int c = (2 * kp) >> 6, klocal = (2 * kp) & 63;
    size_t blk = ((size_t)t * (I >> 6) + c) * 32768;
    uint32_t off = SW128((uint32_t)(n * 128 + klocal * 2));
    *reinterpret_cast<uint32_t*>(dst + blk + off) = hw;
    *reinterpret_cast<uint32_t*>(dst + blk + 16384 + off) = lw;
}

// Fused A pack: one block per (mtile, kchunk); reads the 128x64 activation tile
// once and writes all 9 packed blocks (8 basis subs + 1 x tile).
__global__ void pack_a_kernel(const float* __restrict__ act,
                              char* __restrict__ ab, int I, int nkc) {
    int bid = blockIdx.x;
    int kc = bid % nkc;
    int mt = bid / nkc;
    char* base = ab + ((size_t)mt * nkc + kc) * 9 * 32768;
    int tid = threadIdx.x;
    // 2048 (mloc, c4) tasks: each handles 4 consecutive input cols
    #pragma unroll
    for (int rr = 0; rr < 8; ++rr) {
        int v = rr * 256 + tid;
        int mloc = v >> 4, c4 = v & 15;
        float4 xv = *reinterpret_cast<const float4*>(
            &act[(size_t)(mt * 128 + mloc) * I + kc * 64 + c4 * 4]);
        // x tile (sub 8)
        {
            char* blk = base + 8 * 32768;
            uint32_t h0w, l0w, h1w, l1w;
            bfsplit2(xv.x, xv.y, h0w, l0w);
            bfsplit2(xv.z, xv.w, h1w, l1w);
            uint32_t off = SW128((uint32_t)(mloc * 128 + c4 * 8));
            *reinterpret_cast<uint2*>(blk + off) = make_uint2(h0w, h1w);
            *reinterpret_cast<uint2*>(blk + 16384 + off) = make_uint2(l0w, l1w);
        }
        // basis tiles: 4 values -> 4 il slots in sub = c4>>1, il base = (c4&1)*4
        float xs4[4] = {xv.x, xv.y, xv.z, xv.w};
        int sub = c4 >> 1;
        char* bblk = base + sub * 32768;
        #pragma unroll
        for (int j = 0; j < 2; ++j) {
            // pair (2j, 2j+1) -> il = (c4&1)*4 + 2j .. +1
            #pragma unroll
            for (int e = 0; e < 2; ++e) {
                int il = (c4 & 1) * 4 + j * 2 + e;
                float d = xs4[j * 2 + e] + 0.044f;
                float ee = __expf(-3.125f * d * d);
                float u = __expf(0.05f * d);
                float vv[8];
                vv[0] = ee;
                #pragma unroll
                for (int g = 1; g < 8; ++g) vv[g] = vv[g - 1] * u * RAT[g - 1];
                uint32_t hw[4], lw[4];
                #pragma unroll
                for (int qq = 0; qq < 4; ++qq)
                    bfsplit2(vv[2 * qq], vv[2 * qq + 1], hw[qq], lw[qq]);
                uint32_t off = SW128((uint32_t)(mloc * 128 + il * 16));
                *reinterpret_cast<uint4*>(bblk + off) =
                    make_uint4(hw[0], hw[1], hw[2], hw[3]);
                *reinterpret_cast<uint4*>(bblk + 16384 + off) =
                    make_uint4(lw[0], lw[1], lw[2], lw[3]);
            }
        }
    }
}

// ---------------- SMEM: 3-stage ring, 64KB per stage ----------------
static constexpr int STAGE_STRIDE = 65536;
static constexpr int NSTAGE = 3;
static constexpr int SMEM_SZ = NSTAGE * STAGE_STRIDE;   // 192KB
static constexpr int SMEM_DYN = SMEM_SZ + 1024;

// ---------------- main kernel: 16 warps (4x4), warp tile 32x32 (R7 config) ----
__global__ __launch_bounds__(THREADS, 1)
void kan_mma_kernel(const char* __restrict__ ab,
                    const char* __restrict__ swp,
                    const char* __restrict__ bwp,
                    const float* __restrict__ sbp,
                    const float* __restrict__ ssp,
                    const float* __restrict__ snp,
                    float* __restrict__ outp,
                    int nkc, int O,
                    uint32_t nk0, uint32_t nk1) {
    extern __shared__ char raw[];
    const uint32_t rawu = smem_u32(raw);
    const uint32_t sbase = (rawu + 1023u) & ~1023u;

    const int tid = threadIdx.x;
    const int wid = tid >> 5;
    const int lid = tid & 31;
    const int wm  = wid >> 2;       // 0..3
    const int wn  = wid & 3;        // 0..3
    const int m0  = blockIdx.y * 128;
    const int n0  = blockIdx.x * 128;   // n fastest
    const int mt  = blockIdx.y;

    const int q = lid >> 3, r = lid & 7;
    const int rowA_l = r + (q & 1) * 8;
    const int kselA  = (q >> 1) * 16;
    const int rowB_l = r + (q >> 1) * 8;
    const int kselB  = (q & 1) * 16;

    float accS[2][4][4];
    float accB[2][4][4];
    #pragma unroll
    for (int a = 0; a < 2; ++a)
        #pragma unroll
        for (int b = 0; b < 4; ++b)
            #pragma unroll
            for (int e = 0; e < 4; ++e) { accS[a][b][e] = 0.f; accB[a][b][e] = 0.f; }

    const size_t a_tile = (size_t)mt * nkc;
    const size_t b_tile = (size_t)(n0 >> 7) * nkc;
    const int total = nkc * 9;

    auto issue_stage = [&](int s) {
        int kc = s / 9, sub = s - kc * 9;
        uint32_t dst = sbase + (s % NSTAGE) * STAGE_STRIDE;
        const char* asrc = ab + ((a_tile + kc) * 9 + sub) * 32768;
        const char* bsrc = (sub < 8)
            ? swp + (((b_tile + kc) * 8) + sub) * 32768
            : bwp + (b_tile + kc) * 32768;
        #pragma unroll
        for (int rr = 0; rr < 4; ++rr) {
            uint32_t off = (uint32_t)(rr * THREADS + tid) * 16;
            CP_ASYNC16(dst + off, asrc + off);
        }
        #pragma unroll
        for (int rr = 0; rr < 4; ++rr) {
            uint32_t off = (uint32_t)(rr * THREADS + tid) * 16;
            CP_ASYNC16(dst + 32768 + off, bsrc + off);
        }
        CP_COMMIT();
    };

    auto do_mma = [&](int buf, float (&acc)[2][4][4]) {
        const uint32_t Ah = sbase + buf * STAGE_STRIDE;
        const uint32_t Al = Ah + 16384;
        const uint32_t Bh = Ah + 32768;
        const uint32_t Bl = Ah + 49152;
        #pragma unroll
        for (int k16 = 0; k16 < 4; ++k16) {
            const int kbyt = k16 * 32;
            uint32_t ah[2][4], al[2][4];
            #pragma unroll
            for (int mf = 0; mf < 2; ++mf) {
                int m = wm * 32 + mf * 16 + rowA_l;
                uint32_t off = (uint32_t)(m * 128)
                             + (((uint32_t)(kbyt + kselA)) ^ ((m * 16) & 0x70));
                LDSM4(ah[mf], Ah + off);
                LDSM4(al[mf], Al + off);
            }
            uint32_t bh[2][4], bl[2][4];
            #pragma unroll
            for (int nb = 0; nb < 2; ++nb) {
                int n = wn * 32 + nb * 16 + rowB_l;
                uint32_t off = (uint32_t)(n * 128)
                             + (((uint32_t)(kbyt + kselB)) ^ ((n * 16) & 0x70));
                LDSM4(bh[nb], Bh + off);
                LDSM4(bl[nb], Bl + off);
            }
            #pragma unroll
            for (int mf = 0; mf < 2; ++mf)
                #pragma unroll
                for (int nf = 0; nf < 4; ++nf) {
                    const int nb = nf >> 1, ri = (nf & 1) * 2;
                    MMA_BF16(acc[mf][nf], ah[mf], bh[nb][ri], bh[nb][ri + 1]);
                    MMA_BF16(acc[mf][nf], ah[mf], bl[nb][ri], bl[nb][ri + 1]);
                    MMA_BF16(acc[mf][nf], al[mf], bh[nb][ri], bh[nb][ri + 1]);
                }
        }
    };

    issue_stage(0);
    issue_stage(1);
    for (int s = 0; s < total; ++s) {
        if (s < total - 1) { CP_WAIT1(); } else { CP_WAIT0(); }
        __syncthreads();
        if (s + 2 < total) issue_stage(s + 2);   // copies overlap this stage's MMA
        int sub = s % 9;
        if (sub == 8) do_mma(s % NSTAGE, accB);
        else          do_mma(s % NSTAGE, accS);
    }

    // ---------------- epilogue ----------------
    const float snv = *snp;
    const int rq = lid >> 2, cq = (lid & 3) * 2;
    #pragma unroll
    for (int mf = 0; mf < 2; ++mf) {
        #pragma unroll
        for (int nf = 0; nf < 4; ++nf) {
            #pragma unroll
            for (int half = 0; half < 2; ++half) {
                int b = m0 + wm * 32 + mf * 16 + rq + half * 8;
                int obase = n0 + wn * 32 + nf * 8 + cq;
                float2 res;
                #pragma unroll
                for (int e = 0; e < 2; ++e) {
                    int o = obase + e;
                    float sv = accS[mf][nf][half * 2 + e];
                    float bv = accB[mf][nf][half * 2 + e];
                    float sg = 1.0f / (1.0f + __expf(-bv));
                    uint32_t li = (uint32_t)b * (uint32_t)O + (uint32_t)o;
                    uint32_t r0, r1;
                    threefry2x32_dev(nk0, nk1, 0u, li, r0, r1);
                    uint32_t bits = r0 ^ r1;
                    float f = __uint_as_float((bits >> 9) | 0x3f800000u) - 1.0f;
                    float uu = fmaxf(-0.99999994f, fmaf(f, 2.0f, -0.99999994f));
                    float nz = 1.41421356f * erfinvf(uu);
                    float val = bv * sg * sbp[o] + sv * ssp[o] + nz * snv;
                    if (e == 0) res.x = val; else res.y = val;
                }
                *reinterpret_cast<float2*>(&outp[(size_t)b * O + obase]) = res;
            }
        }
    }
}

// ---------------- launch ----------------
extern "C" void kernel_launch(void* const* d_in, const int* in_sizes, int n_in,
                              void* d_out, int out_size) {
    const float* x = (const float*)d_in[0];
    const float* sw[4]; const float* bw[4]; const float* sb[4];
    const float* ss[4]; const float* sn[4];
    for (int li = 0; li < 4; ++li) {
        sw[li] = (const float*)d_in[1 + 5 * li + 0];
        bw[li] = (const float*)d_in[1 + 5 * li + 1];
        sb[li] = (const float*)d_in[1 + 5 * li + 2];
        ss[li] = (const float*)d_in[1 + 5 * li + 3];
        sn[li] = (const float*)d_in[1 + 5 * li + 4];
    }
    const int B = in_sizes[0] / 1024;   // 8192
    float* out  = (float*)d_out;
    float* xrec = out;
    float* z    = out + (size_t)B * 1024;

    float* h0; cudaGetSymbolAddress((void**)&h0, g_h0);
    float* h2; cudaGetSymbolAddress((void**)&h2, g_h2);
    char* swp; cudaGetSymbolAddress((void**)&swp, g_swp);
    char* bwp; cudaGetSymbolAddress((void**)&bwp, g_bwp);
    char* ab;  cudaGetSymbolAddress((void**)&ab, g_ab);

    const int Is[4] = {1024, 2048, 256, 2048};
    const int Os[4] = {2048, 256, 2048, 1024};
    size_t sw_off[4], bw_off[4];
    size_t so = 0, bo = 0;
    for (int li = 0; li < 4; ++li) {
        sw_off[li] = so; bw_off[li] = bo;
        so += (size_t)(Os[li] / 128) * (Is[li] / 64) * 8 * 32768;
        bo += (size_t)(Os[li] / 128) * (Is[li] / 64) * 32768;
    }

    uint32_t fk0[4], fk1[4];
    for (int li = 0; li < 4; ++li)
        threefry2x32_host(0u, 42u, 0u, (uint32_t)li, fk0[li], fk1[li]);

    cudaFuncSetAttribute(kan_mma_kernel,
                         cudaFuncAttributeMaxDynamicSharedMemorySize, SMEM_DYN);

    const int mtiles = B / 128;
    dim3 blk(THREADS);
    const float* ins[4]  = {x, h0, z, h2};
    float* outs[4]       = {h0, z, h2, xrec};

    // all weight packs first (input-independent)
    for (int li = 0; li < 4; ++li) {
        size_t tot = (size_t)Is[li] * Os[li] * 4;
        pack_sw_kernel<<<(unsigned)((tot + 255) / 256), 256>>>(
            sw[li], swp + sw_off[li], Is[li], Os[li]);
        size_t totb = (size_t)Os[li] * (Is[li] / 2);
        pack_bw_kernel<<<(unsigned)((totb + 255) / 256), 256>>>(
            bw[li], bwp + bw_off[li], Is[li], Os[li]);
    }

    for (int li = 0; li < 4; ++li) {
        const int nkc = Is[li] / 64;
        pack_a_kernel<<<(unsigned)(mtiles * nkc), 256>>>(ins[li], ab, Is[li], nkc);
        dim3 g(Os[li] / 128, mtiles);
        kan_mma_kernel<<<g, blk, SMEM_DYN>>>(
            ab, swp + sw_off[li], bwp + bw_off[li],
            sb[li], ss[li], sn[li], outs[li],
            Is[li] / 64, Os[li], fk0[li], fk1[li]);
    }
}

// round 11
// speedup vs baseline: 1.1671x; 1.1176x over previous
#include <cuda_runtime.h>
#include <cuda_bf16.h>
#include <cstdint>
#include <cstddef>

#define THREADS 512

// Scratch activations (fp32)
__device__ float g_h0[8192u * 2048u];
__device__ float g_h2[8192u * 2048u];

// Packed pre-swizzled bf16 hi/lo weights:
// sw blocks: per (layer, ntile, kchunk64, sub): 32KB = [hi 16KB | lo 16KB]
// bw blocks: per (layer, ntile, kchunk64): 32KB
__device__ __align__(128) char g_swp[167772160];   // 160MB
__device__ __align__(128) char g_bwp[20971520];    // 20MB
// Packed A-blocks (per layer, reused): per (mtile, kchunk64, sub 0..8): 32KB
__device__ __align__(128) char g_ab[603979776];

// Gaussian basis recurrence: e_g = e0 * u^g * exp(-2e-4*g^2)
__constant__ float RAT[7] = {0.99980002f, 0.99940018f, 0.99900050f,
                             0.99860098f, 0.99820162f, 0.99780242f, 0.99740338f};

// ---------------- threefry2x32 (JAX-compatible, validated) ----------------
__device__ __forceinline__ uint32_t rotl32d(uint32_t v, int d) {
    return __funnelshift_l(v, v, d);
}
__device__ __forceinline__ void threefry2x32_dev(uint32_t k0, uint32_t k1,
                                                 uint32_t c0, uint32_t c1,
                                                 uint32_t& o0, uint32_t& o1) {
    uint32_t ks2 = k0 ^ k1 ^ 0x1BD11BDAu;
    uint32_t x0 = c0 + k0, x1 = c1 + k1;
#define TF_RND(r) { x0 += x1; x1 = rotl32d(x1, r); x1 ^= x0; }
    TF_RND(13) TF_RND(15) TF_RND(26) TF_RND(6)
    x0 += k1;  x1 += ks2 + 1u;
    TF_RND(17) TF_RND(29) TF_RND(16) TF_RND(24)
    x0 += ks2; x1 += k0 + 2u;
    TF_RND(13) TF_RND(15) TF_RND(26) TF_RND(6)
    x0 += k0;  x1 += k1 + 3u;
    TF_RND(17) TF_RND(29) TF_RND(16) TF_RND(24)
    x0 += k1;  x1 += ks2 + 4u;
    TF_RND(13) TF_RND(15) TF_RND(26) TF_RND(6)
    x0 += ks2; x1 += k0 + 5u;
#undef TF_RND
    o0 = x0; o1 = x1;
}
static inline uint32_t rotl32h(uint32_t v, int d) {
    return (v << d) | (v >> (32 - d));
}
static void threefry2x32_host(uint32_t k0, uint32_t k1, uint32_t c0, uint32_t c1,
                              uint32_t& o0, uint32_t& o1) {
    uint32_t ks2 = k0 ^ k1 ^ 0x1BD11BDAu;
    uint32_t x0 = c0 + k0, x1 = c1 + k1;
#define TF_RND(r) { x0 += x1; x1 = rotl32h(x1, r); x1 ^= x0; }
    TF_RND(13) TF_RND(15) TF_RND(26) TF_RND(6)
    x0 += k1;  x1 += ks2 + 1u;
    TF_RND(17) TF_RND(29) TF_RND(16) TF_RND(24)
    x0 += ks2; x1 += k0 + 2u;
    TF_RND(13) TF_RND(15) TF_RND(26) TF_RND(6)
    x0 += k0;  x1 += k1 + 3u;
    TF_RND(17) TF_RND(29) TF_RND(16) TF_RND(24)
    x0 += k1;  x1 += ks2 + 4u;
    TF_RND(13) TF_RND(15) TF_RND(26) TF_RND(6)
    x0 += ks2; x1 += k0 + 5u;
#undef TF_RND
    o0 = x0; o1 = x1;
}

// ---------------- helpers ----------------
__device__ __forceinline__ uint32_t smem_u32(const void* p) {
    uint32_t a;
    asm("{ .reg .u64 t; cvta.to.shared.u64 t, %1; cvt.u32.u64 %0, t; }"
        : "=r"(a) : "l"(p));
    return a;
}
#define SW128(o) ((o) ^ ((((uint32_t)(o)) >> 3) & 0x70))

#define LDSM4(rv, a) \
    asm volatile("ldmatrix.sync.aligned.m8n8.x4.shared.b16 {%0,%1,%2,%3}, [%4];" \
        : "=r"((rv)[0]), "=r"((rv)[1]), "=r"((rv)[2]), "=r"((rv)[3]) \
        : "r"(a))

#define MMA_BF16(c, a, b0, b1) \
    asm volatile("mma.sync.aligned.m16n8k16.row.col.f32.bf16.bf16.f32 " \
        "{%0,%1,%2,%3}, {%4,%5,%6,%7}, {%8,%9}, {%0,%1,%2,%3};" \
        : "+f"((c)[0]), "+f"((c)[1]), "+f"((c)[2]), "+f"((c)[3]) \
        : "r"((a)[0]), "r"((a)[1]), "r"((a)[2]), "r"((a)[3]), "r"(b0), "r"(b1))

#define CP_ASYNC16(dst, src) \
    asm volatile("cp.async.cg.shared.global [%0], [%1], 16;" \
                 :: "r"((uint32_t)(dst)), "l"(src) : "memory")
#define CP_COMMIT() asm volatile("cp.async.commit_group;" ::: "memory")
#define CP_WAIT0()  asm volatile("cp.async.wait_group 0;" ::: "memory")
#define CP_WAIT1()  asm volatile("cp.async.wait_group 1;" ::: "memory")

__device__ __forceinline__ void bfsplit2(float a, float b, uint32_t& hi2, uint32_t& lo2) {
    asm("cvt.rn.bf16x2.f32 %0, %1, %2;" : "=r"(hi2) : "f"(b), "f"(a));
    __nv_bfloat162 hv = *reinterpret_cast<__nv_bfloat162*>(&hi2);
    float ra = a - __bfloat162float(hv.x);
    float rb = b - __bfloat162float(hv.y);
    asm("cvt.rn.bf16x2.f32 %0, %1, %2;" : "=r"(lo2) : "f"(rb), "f"(ra));
}

// ---------------- pack kernels (R7 versions) ----------------
__global__ void pack_sw_kernel(const float* __restrict__ sw, char* __restrict__ dst,
                               int I, int O) {
    size_t idx = (size_t)blockIdx.x * blockDim.x + threadIdx.x;
    size_t total = (size_t)I * O * 4;
    if (idx >= total) return;
    int g2 = (int)(idx & 3) * 2;
    size_t rem = idx >> 2;
    int o = (int)(rem % O);
    int i = (int)(rem / O);
    float2 wv = *reinterpret_cast<const float2*>(&sw[((size_t)i * O + o) * 8 + g2]);
    uint32_t hw, lw;
    bfsplit2(wv.x, wv.y, hw, lw);
    int t = o >> 7, n = o & 127, c = i >> 6, s = (i >> 3) & 7, ii = i & 7;
    size_t blk = (((size_t)t * (I >> 6) + c) * 8 + s) * 32768;
    uint32_t off = SW128((uint32_t)(n * 128 + (ii * 8 + g2) * 2));
    *reinterpret_cast<uint32_t*>(dst + blk + off) = hw;
    *reinterpret_cast<uint32_t*>(dst + blk + 16384 + off) = lw;
}

__global__ void pack_bw_kernel(const float* __restrict__ bw, char* __restrict__ dst,
                               int I, int O) {
    size_t idx = (size_t)blockIdx.x * blockDim.x + threadIdx.x;
    size_t total = (size_t)O * (I >> 1);
    if (idx >= total) return;
    int o = (int)(idx % O);
    int kp = (int)(idx / O);
    float b0 = bw[(size_t)(2 * kp) * O + o];
    float b1 = bw[(size_t)(2 * kp + 1) * O + o];
    uint32_t hw, lw;
    bfsplit2(b0, b1, hw, lw);
    int t = o >> 7, n = o & 127;
    int c = (2 * kp) >> 6, klocal = (2 * kp) & 63;
    size_t blk = ((size_t)t * (I >> 6) + c) * 32768;
    uint32_t off = SW128((uint32_t)(n * 128 + klocal * 2));
    *reinterpret_cast<uint32_t*>(dst + blk + off) = hw;
    *reinterpret_cast<uint32_t*>(dst + blk + 16384 + off) = lw;
}

__global__ void pack_bases_kernel(const float* __restrict__ act,
                                  char* __restrict__ ab, int I, int nkc) {
    int bid = blockIdx.x;
    int sub = bid & 7;
    int t = bid >> 3;
    int kc = t % nkc;
    int mt = t / nkc;
    char* blk = ab + (((size_t)mt * nkc + kc) * 9 + sub) * 32768;
    int tid = threadIdx.x;
    #pragma unroll
    for (int rr = 0; rr < 4; ++rr) {
        int v = rr * 256 + tid;
        int mloc = v >> 3, il = v & 7;
        float xv = act[(size_t)(mt * 128 + mloc) * I + kc * 64 + sub * 8 + il];
        float d = xv + 0.044f;
        float e = __expf(-3.125f * d * d);
        float u = __expf(0.05f * d);
        float vv[8];
        vv[0] = e;
        #pragma unroll
        for (int g = 1; g < 8; ++g) vv[g] = vv[g - 1] * u * RAT[g - 1];
        uint32_t hw[4], lw[4];
        #pragma unroll
        for (int qq = 0; qq < 4; ++qq)
            bfsplit2(vv[2 * qq], vv[2 * qq + 1], hw[qq], lw[qq]);
        uint32_t off = SW128((uint32_t)(mloc * 128 + il * 16));
        *reinterpret_cast<uint4*>(blk + off) = make_uint4(hw[0], hw[1], hw[2], hw[3]);
        *reinterpret_cast<uint4*>(blk + 16384 + off) = make_uint4(lw[0], lw[1], lw[2], lw[3]);
    }
}

__global__ void pack_x_kernel(const float* __restrict__ act,
                              char* __restrict__ ab, int I, int nkc) {
    int bid = blockIdx.x;
    int kc = bid % nkc;
    int mt = bid / nkc;
    char* blk = ab + (((size_t)mt * nkc + kc) * 9 + 8) * 32768;
    int tid = threadIdx.x;
    #pragma unroll
    for (int rr = 0; rr < 8; ++rr) {
        int v = rr * 256 + tid;
        int mloc = v >> 4, c4 = v & 15;
        float4 xv = *reinterpret_cast<const float4*>(
            &act[(size_t)(mt * 128 + mloc) * I + kc * 64 + c4 * 4]);
        uint32_t h0w, l0w, h1w, l1w;
        bfsplit2(xv.x, xv.y, h0w, l0w);
        bfsplit2(xv.z, xv.w, h1w, l1w);
        uint32_t off = SW128((uint32_t)(mloc * 128 + c4 * 8));
        *reinterpret_cast<uint2*>(blk + off) = make_uint2(h0w, h1w);
        *reinterpret_cast<uint2*>(blk + 16384 + off) = make_uint2(l0w, l1w);
    }
}

// ---------------- SMEM: 3-stage ring, 64KB per stage ----------------
static constexpr int STAGE_STRIDE = 65536;
static constexpr int NSTAGE = 3;
static constexpr int SMEM_SZ = NSTAGE * STAGE_STRIDE;   // 192KB
static constexpr int SMEM_DYN = SMEM_SZ + 1024;

// ---------------- main kernel: R7 config, byte-identical mainloop ----------------
__global__ __launch_bounds__(THREADS, 1)
void kan_mma_kernel(const char* __restrict__ ab,
                    const char* __restrict__ swp,
                    const char* __restrict__ bwp,
                    const float* __restrict__ sbp,
                    const float* __restrict__ ssp,
                    const float* __restrict__ snp,
                    float* __restrict__ outp,
                    int nkc, int O,
                    uint32_t nk0, uint32_t nk1) {
    extern __shared__ char raw[];
    const uint32_t rawu = smem_u32(raw);
    const uint32_t sbase = (rawu + 1023u) & ~1023u;

    const int tid = threadIdx.x;
    const int wid = tid >> 5;
    const int lid = tid & 31;
    const int wm  = wid >> 2;
    const int wn  = wid & 3;
    const int m0  = blockIdx.y * 128;
    const int n0  = blockIdx.x * 128;   // n fastest
    const int mt  = blockIdx.y;

    const int q = lid >> 3, r = lid & 7;
    const int rowA_l = r + (q & 1) * 8;
    const int kselA  = (q >> 1) * 16;
    const int rowB_l = r + (q >> 1) * 8;
    const int kselB  = (q & 1) * 16;

    float accS[2][4][4];
    float accB[2][4][4];
    #pragma unroll
    for (int a = 0; a < 2; ++a)
        #pragma unroll
        for (int b = 0; b < 4; ++b)
            #pragma unroll
            for (int e = 0; e < 4; ++e) { accS[a][b][e] = 0.f; accB[a][b][e] = 0.f; }

    const size_t a_tile = (size_t)mt * nkc;
    const size_t b_tile = (size_t)(n0 >> 7) * nkc;
    const int total = nkc * 9;

    auto issue_stage = [&](int s) {
        int kc = s / 9, sub = s - kc * 9;
        uint32_t dst = sbase + (s % NSTAGE) * STAGE_STRIDE;
        const char* asrc = ab + ((a_tile + kc) * 9 + sub) * 32768;
        const char* bsrc = (sub < 8)
            ? swp + (((b_tile + kc) * 8) + sub) * 32768
            : bwp + (b_tile + kc) * 32768;
        #pragma unroll
        for (int rr = 0; rr < 4; ++rr) {
            uint32_t off = (uint32_t)(rr * THREADS + tid) * 16;
            CP_ASYNC16(dst + off, asrc + off);
        }
        #pragma unroll
        for (int rr = 0; rr < 4; ++rr) {
            uint32_t off = (uint32_t)(rr * THREADS + tid) * 16;
            CP_ASYNC16(dst + 32768 + off, bsrc + off);
        }
        CP_COMMIT();
    };

    auto do_mma = [&](int buf, float (&acc)[2][4][4]) {
        const uint32_t Ah = sbase + buf * STAGE_STRIDE;
        const uint32_t Al = Ah + 16384;
        const uint32_t Bh = Ah + 32768;
        const uint32_t Bl = Ah + 49152;
        #pragma unroll
        for (int k16 = 0; k16 < 4; ++k16) {
            const int kbyt = k16 * 32;
            uint32_t ah[2][4], al[2][4];
            #pragma unroll
            for (int mf = 0; mf < 2; ++mf) {
                int m = wm * 32 + mf * 16 + rowA_l;
                uint32_t off = (uint32_t)(m * 128)
                             + (((uint32_t)(kbyt + kselA)) ^ ((m * 16) & 0x70));
                LDSM4(ah[mf], Ah + off);
                LDSM4(al[mf], Al + off);
            }
            uint32_t bh[2][4], bl[2][4];
            #pragma unroll
            for (int nb = 0; nb < 2; ++nb) {
                int n = wn * 32 + nb * 16 + rowB_l;
                uint32_t off = (uint32_t)(n * 128)
                             + (((uint32_t)(kbyt + kselB)) ^ ((n * 16) & 0x70));
                LDSM4(bh[nb], Bh + off);
                LDSM4(bl[nb], Bl + off);
            }
            #pragma unroll
            for (int mf = 0; mf < 2; ++mf)
                #pragma unroll
                for (int nf = 0; nf < 4; ++nf) {
                    const int nb = nf >> 1, ri = (nf & 1) * 2;
                    MMA_BF16(acc[mf][nf], ah[mf], bh[nb][ri], bh[nb][ri + 1]);
                    MMA_BF16(acc[mf][nf], ah[mf], bl[nb][ri], bl[nb][ri + 1]);
                    MMA_BF16(acc[mf][nf], al[mf], bh[nb][ri], bh[nb][ri + 1]);
                }
        }
    };

    issue_stage(0);
    issue_stage(1);
    for (int s = 0; s < total; ++s) {
        if (s < total - 1) { CP_WAIT1(); } else { CP_WAIT0(); }
        __syncthreads();
        int sub = s % 9;
        if (sub == 8) do_mma(s % NSTAGE, accB);
        else          do_mma(s % NSTAGE, accS);
        if (s + 2 < total) issue_stage(s + 2);   // R7 order: issue AFTER mma
    }

    // ---------------- epilogue ----------------
    const float snv = *snp;
    const int rq = lid >> 2, cq = (lid & 3) * 2;
    #pragma unroll
    for (int mf = 0; mf < 2; ++mf) {
        #pragma unroll
        for (int nf = 0; nf < 4; ++nf) {
            #pragma unroll
            for (int half = 0; half < 2; ++half) {
                int b = m0 + wm * 32 + mf * 16 + rq + half * 8;
                int obase = n0 + wn * 32 + nf * 8 + cq;
                float2 res;
                #pragma unroll
                for (int e = 0; e < 2; ++e) {
                    int o = obase + e;
                    float sv = accS[mf][nf][half * 2 + e];
                    float bv = accB[mf][nf][half * 2 + e];
                    float sg = 1.0f / (1.0f + __expf(-bv));
                    uint32_t li = (uint32_t)b * (uint32_t)O + (uint32_t)o;
                    uint32_t r0, r1;
                    threefry2x32_dev(nk0, nk1, 0u, li, r0, r1);
                    uint32_t bits = r0 ^ r1;
                    float f = __uint_as_float((bits >> 9) | 0x3f800000u) - 1.0f;
                    float uu = fmaxf(-0.99999994f, fmaf(f, 2.0f, -0.99999994f));
                    float nz = 1.41421356f * erfinvf(uu);
                    float val = bv * sg * sbp[o] + sv * ssp[o] + nz * snv;
                    if (e == 0) res.x = val; else res.y = val;
                }
                *reinterpret_cast<float2*>(&outp[(size_t)b * O + obase]) = res;
            }
        }
    }
}

// ---------------- launch: side-stream weight packs overlapped with mains ------
extern "C" void kernel_launch(void* const* d_in, const int* in_sizes, int n_in,
                              void* d_out, int out_size) {
    const float* x = (const float*)d_in[0];
    const float* sw[4]; const float* bw[4]; const float* sb[4];
    const float* ss[4]; const float* sn[4];
    for (int li = 0; li < 4; ++li) {
        sw[li] = (const float*)d_in[1 + 5 * li + 0];
        bw[li] = (const float*)d_in[1 + 5 * li + 1];
        sb[li] = (const float*)d_in[1 + 5 * li + 2];
        ss[li] = (const float*)d_in[1 + 5 * li + 3];
        sn[li] = (const float*)d_in[1 + 5 * li + 4];
    }
    const int B = in_sizes[0] / 1024;   // 8192
    float* out  = (float*)d_out;
    float* xrec = out;
    float* z    = out + (size_t)B * 1024;

    float* h0; cudaGetSymbolAddress((void**)&h0, g_h0);
    float* h2; cudaGetSymbolAddress((void**)&h2, g_h2);
    char* swp; cudaGetSymbolAddress((void**)&swp, g_swp);
    char* bwp; cudaGetSymbolAddress((void**)&bwp, g_bwp);
    char* ab;  cudaGetSymbolAddress((void**)&ab, g_ab);

    const int Is[4] = {1024, 2048, 256, 2048};
    const int Os[4] = {2048, 256, 2048, 1024};
    size_t sw_off[4], bw_off[4];
    size_t so = 0, bo = 0;
    for (int li = 0; li < 4; ++li) {
        sw_off[li] = so; bw_off[li] = bo;
        so += (size_t)(Os[li] / 128) * (Is[li] / 64) * 8 * 32768;
        bo += (size_t)(Os[li] / 128) * (Is[li] / 64) * 32768;
    }

    uint32_t fk0[4], fk1[4];
    for (int li = 0; li < 4; ++li)
        threefry2x32_host(0u, 42u, 0u, (uint32_t)li, fk0[li], fk1[li]);

    cudaFuncSetAttribute(kan_mma_kernel,
                         cudaFuncAttributeMaxDynamicSharedMemorySize, SMEM_DYN);

    // One-time side stream + events (created once; no device memory involved).
    static cudaStream_t side = [] {
        cudaStream_t s; cudaStreamCreateWithFlags(&s, cudaStreamNonBlocking); return s;
    }();
    static cudaEvent_t evFork = [] {
        cudaEvent_t e; cudaEventCreateWithFlags(&e, cudaEventDisableTiming); return e;
    }();
    static cudaEvent_t evW[4] = {
        [] { cudaEvent_t e; cudaEventCreateWithFlags(&e, cudaEventDisableTiming); return e; }(),
        [] { cudaEvent_t e; cudaEventCreateWithFlags(&e, cudaEventDisableTiming); return e; }(),
        [] { cudaEvent_t e; cudaEventCreateWithFlags(&e, cudaEventDisableTiming); return e; }(),
        [] { cudaEvent_t e; cudaEventCreateWithFlags(&e, cudaEventDisableTiming); return e; }()
    };

    const int mtiles = B / 128;
    dim3 blk(THREADS);
    const float* ins[4]  = {x, h0, z, h2};
    float* outs[4]       = {h0, z, h2, xrec};

    auto pack_w_side = [&](int li) {
        size_t tot = (size_t)Is[li] * Os[li] * 4;
        pack_sw_kernel<<<(unsigned)((tot + 255) / 256), 256, 0, side>>>(
            sw[li], swp + sw_off[li], Is[li], Os[li]);
        size_t totb = (size_t)Os[li] * (Is[li] / 2);
        pack_bw_kernel<<<(unsigned)((totb + 255) / 256), 256, 0, side>>>(
            bw[li], bwp + bw_off[li], Is[li], Os[li]);
        cudaEventRecord(evW[li], side);
    };
    auto pack_a_main = [&](int li) {
        const int nkc = Is[li] / 64;
        pack_bases_kernel<<<(unsigned)(mtiles * nkc * 8), 256>>>(ins[li], ab, Is[li], nkc);
        pack_x_kernel<<<(unsigned)(mtiles * nkc), 256>>>(ins[li], ab, Is[li], nkc);
    };
    auto run_main = [&](int li) {
        dim3 g(Os[li] / 128, mtiles);
        kan_mma_kernel<<<g, blk, SMEM_DYN>>>(
            ab, swp + sw_off[li], bwp + bw_off[li],
            sb[li], ss[li], sn[li], outs[li],
            Is[li] / 64, Os[li], fk0[li], fk1[li]);
    };

    // Fork side stream off the capture (null) stream; all weight packs run there,
    // overlapping with A-packs and main kernels on the null stream.
    cudaEventRecord(evFork, 0);
    cudaStreamWaitEvent(side, evFork, 0);
    for (int li = 0; li < 4; ++li) pack_w_side(li);

    for (int li = 0; li < 4; ++li) {
        pack_a_main(li);                       // depends on previous main (same stream)
        cudaStreamWaitEvent(0, evW[li], 0);    // join weight packs for this layer
        run_main(li);
    }
}